// round 7
// baseline (speedup 1.0000x reference)
#include <cuda_runtime.h>
#include <cuda_bf16.h>
#include <cstdint>
#include <math.h>

#define B_ 16
#define T_ 2048
#define C_ 1024
#define H_ 64
#define ROWS_ (B_ * T_)   // 32768

// Scratch for projected q, k, v (fp32, consumed by attn_kernel)
__device__ float g_q[ROWS_ * H_];
__device__ float g_k[ROWS_ * H_];
__device__ float g_v[ROWS_ * H_];

// Pre-transposed, bf16-split weights: [w][n=64][k=1024]
__device__ __align__(16) __nv_bfloat16 g_wT_hi[3 * 64 * 1024];
__device__ __align__(16) __nv_bfloat16 g_wT_lo[3 * 64 * 1024];

// log2(e) / sqrt(H) folded into q so attention uses exp2f directly
#define QSCALE 0.18033688011112042f   // 1.4426950408889634f * 0.125f

__device__ __forceinline__ uint32_t pack_bf16x2(float a, float b) {
    __nv_bfloat162 t = __floats2bfloat162_rn(a, b);
    return *(uint32_t*)&t;
}

// mma.sync m16n8k16 bf16 (sm_80+ PTX, runs on tensor pipe as HMMA on sm_103)
__device__ __forceinline__ void mma_bf16(float* d, const uint32_t* a,
                                         uint32_t b0, uint32_t b1) {
    asm volatile(
        "mma.sync.aligned.m16n8k16.row.col.f32.bf16.bf16.f32 "
        "{%0,%1,%2,%3}, {%4,%5,%6,%7}, {%8,%9}, {%0,%1,%2,%3};"
        : "+f"(d[0]), "+f"(d[1]), "+f"(d[2]), "+f"(d[3])
        : "r"(a[0]), "r"(a[1]), "r"(a[2]), "r"(a[3]), "r"(b0), "r"(b1));
}

// ---------------------------------------------------------------------------
// Kernel 0: transpose + bf16 hi/lo split of the three weight matrices.
// W[1024,64] -> g_wT_{hi,lo}[w][n][k].  grid = 3*64, block = 256.
// ---------------------------------------------------------------------------
__global__ void convert_w_kernel(const float* __restrict__ wq,
                                 const float* __restrict__ wk,
                                 const float* __restrict__ wv)
{
    const int w = blockIdx.x >> 6;
    const int n = blockIdx.x & 63;
    const float* __restrict__ src = (w == 0) ? wq : (w == 1) ? wk : wv;
    const int base = w * 65536 + n * 1024;
#pragma unroll
    for (int i = 0; i < 4; i++) {
        int k = threadIdx.x + i * 256;
        float v = src[(size_t)k * 64 + n];
        __nv_bfloat16 h = __float2bfloat16(v);
        float r = v - __bfloat162float(h);
        g_wT_hi[base + k] = h;
        g_wT_lo[base + k] = __float2bfloat16(r);
    }
}

// ---------------------------------------------------------------------------
// Kernel 1: QKV projection via mma.sync bf16, 3-term split precision.
// CTA: 128 rows x all 3 outputs (N=64 each).  512 threads = 16 warps,
// warp grid 4(M: 32 rows) x 4(N: 16 cols).  K staged in 16 chunks of 64.
// Smem: A hi/lo [128][64] bf16 swizzled; B[w][hi/lo][64][64] bf16 swizzled.
// ---------------------------------------------------------------------------
#define OFF_AHI 0
#define OFF_ALO 16384
#define OFF_B   32768                 // + (w*2 + hilo)*8192
#define PROJ_SMEM 81920

__global__ __launch_bounds__(512, 1)
void qkv_proj_mma(const float* __restrict__ x)
{
    extern __shared__ char smem[];
    const int tid = threadIdx.x;
    const int wid = tid >> 5;
    const int lane = tid & 31;
    const int g  = lane >> 2;     // group id (row within fragment)
    const int tg = lane & 3;      // thread in group
    const int warpM = wid >> 2;   // 0..3 -> rows warpM*32
    const int warpN = wid & 3;    // 0..3 -> cols warpN*16
    const int mBase = blockIdx.x * 128;

    float acc[3][2][2][4];
#pragma unroll
    for (int w = 0; w < 3; w++)
#pragma unroll
        for (int mt = 0; mt < 2; mt++)
#pragma unroll
            for (int nt = 0; nt < 2; nt++)
#pragma unroll
                for (int e = 0; e < 4; e++) acc[w][mt][nt][e] = 0.0f;

    for (int kc = 0; kc < 16; kc++) {
        // ---- stage A chunk: X[128 rows, 64 k] fp32 -> bf16 hi/lo, swizzled ----
#pragma unroll
        for (int it = 0; it < 4; it++) {
            int idx = tid + it * 512;
            int r = idx >> 4, c4 = idx & 15;
            float4 v = *(const float4*)&x[(size_t)(mBase + r) * C_ + kc * 64 + c4 * 4];
            uint32_t swz = (uint32_t)((r & 7) << 4);
            uint32_t off = (uint32_t)(r * 128) + (((uint32_t)(c4 * 8)) ^ swz);
            __nv_bfloat16 hx = __float2bfloat16(v.x);
            __nv_bfloat16 hy = __float2bfloat16(v.y);
            __nv_bfloat16 hz = __float2bfloat16(v.z);
            __nv_bfloat16 hw = __float2bfloat16(v.w);
            uint2 hp, lp;
            __nv_bfloat162 h01 = __nv_bfloat162(hx, hy), h23 = __nv_bfloat162(hz, hw);
            hp.x = *(uint32_t*)&h01; hp.y = *(uint32_t*)&h23;
            lp.x = pack_bf16x2(v.x - __bfloat162float(hx), v.y - __bfloat162float(hy));
            lp.y = pack_bf16x2(v.z - __bfloat162float(hz), v.w - __bfloat162float(hw));
            *(uint2*)(smem + OFF_AHI + off) = hp;
            *(uint2*)(smem + OFF_ALO + off) = lp;
        }
        // ---- stage B chunks (pre-converted bf16): [w][hi/lo][64n][64k] ----
        // 3 w * 64 n * 8 u = 1536 vectors; 512 threads -> 3 iterations.
#pragma unroll
        for (int it = 0; it < 3; it++) {
            int idx = tid + it * 512;
            int u = idx & 7, n = (idx >> 3) & 63, w = idx >> 9;
            int src = w * 65536 + n * 1024 + kc * 64 + u * 8;
            uint32_t swz = (uint32_t)((n & 7) << 4);
            uint32_t off = (uint32_t)(n * 128) + (((uint32_t)(u * 16)) ^ swz);
            *(uint4*)(smem + OFF_B + (w * 2) * 8192 + off)     = *(const uint4*)&g_wT_hi[src];
            *(uint4*)(smem + OFF_B + (w * 2 + 1) * 8192 + off) = *(const uint4*)&g_wT_lo[src];
        }
        __syncthreads();

        // ---- mma over this chunk: 4 k-steps of k16 ----
#pragma unroll
        for (int ks = 0; ks < 4; ks++) {
            const uint32_t c2 = (uint32_t)(ks * 32 + tg * 4);
            uint32_t Ah[2][4], Al[2][4];
#pragma unroll
            for (int mt = 0; mt < 2; mt++) {
                int r0 = warpM * 32 + mt * 16 + g;
                uint32_t swz = (uint32_t)((r0 & 7) << 4);
                uint32_t row0 = (uint32_t)(r0 * 128);
                uint32_t row1 = (uint32_t)((r0 + 8) * 128);
                uint32_t cA = c2 ^ swz, cB = (c2 + 16) ^ swz;
                Ah[mt][0] = *(const uint32_t*)(smem + OFF_AHI + row0 + cA);
                Ah[mt][1] = *(const uint32_t*)(smem + OFF_AHI + row1 + cA);
                Ah[mt][2] = *(const uint32_t*)(smem + OFF_AHI + row0 + cB);
                Ah[mt][3] = *(const uint32_t*)(smem + OFF_AHI + row1 + cB);
                Al[mt][0] = *(const uint32_t*)(smem + OFF_ALO + row0 + cA);
                Al[mt][1] = *(const uint32_t*)(smem + OFF_ALO + row1 + cA);
                Al[mt][2] = *(const uint32_t*)(smem + OFF_ALO + row0 + cB);
                Al[mt][3] = *(const uint32_t*)(smem + OFF_ALO + row1 + cB);
            }
#pragma unroll
            for (int w = 0; w < 3; w++) {
#pragma unroll
                for (int nt = 0; nt < 2; nt++) {
                    int n0 = warpN * 16 + nt * 8 + g;
                    uint32_t swz = (uint32_t)((n0 & 7) << 4);
                    uint32_t brow = (uint32_t)(n0 * 128);
                    uint32_t cA = c2 ^ swz, cB = (c2 + 16) ^ swz;
                    const char* bh = smem + OFF_B + (w * 2) * 8192;
                    const char* bl = smem + OFF_B + (w * 2 + 1) * 8192;
                    uint32_t bh0 = *(const uint32_t*)(bh + brow + cA);
                    uint32_t bh1 = *(const uint32_t*)(bh + brow + cB);
                    uint32_t bl0 = *(const uint32_t*)(bl + brow + cA);
                    uint32_t bl1 = *(const uint32_t*)(bl + brow + cB);
#pragma unroll
                    for (int mt = 0; mt < 2; mt++) {
                        mma_bf16(acc[w][mt][nt], Ah[mt], bh0, bh1);
                        mma_bf16(acc[w][mt][nt], Ah[mt], bl0, bl1);
                        mma_bf16(acc[w][mt][nt], Al[mt], bh0, bh1);
                    }
                }
            }
        }
        __syncthreads();
    }

    // ---- epilogue: fragments -> g_q/g_k/g_v (fp32) ----
#pragma unroll
    for (int w = 0; w < 3; w++) {
        float* __restrict__ dst = (w == 0) ? g_q : (w == 1) ? g_k : g_v;
        const float s = (w == 0) ? QSCALE : 1.0f;
#pragma unroll
        for (int mt = 0; mt < 2; mt++) {
#pragma unroll
            for (int nt = 0; nt < 2; nt++) {
                int row = mBase + warpM * 32 + mt * 16 + g;
                int col = warpN * 16 + nt * 8 + 2 * tg;
                float2 v0 = { acc[w][mt][nt][0] * s, acc[w][mt][nt][1] * s };
                float2 v1 = { acc[w][mt][nt][2] * s, acc[w][mt][nt][3] * s };
                *(float2*)&dst[(size_t)row * H_ + col] = v0;
                *(float2*)&dst[(size_t)(row + 8) * H_ + col] = v1;
            }
        }
    }
}

// ---------------------------------------------------------------------------
// Kernel 2: causal flash attention (unchanged — passing at 254us)
// ---------------------------------------------------------------------------
__global__ __launch_bounds__(128, 3)
void attn_kernel(float* __restrict__ out)
{
    __shared__ float Qs[64][64];
    __shared__ float KPs[64][64];   // K (swizzled) then re-used as P (plain)
    __shared__ float Vs[64][64];

    const int tid = threadIdx.x;
    const int j = tid & 15;
    const int i = tid >> 4;

    const int b = blockIdx.x >> 4;
    const int p = blockIdx.x & 15;
    const size_t bRow = (size_t)b * T_;

    for (int half = 0; half < 2; half++) {
        const int qt = (half == 0) ? p : (31 - p);
        const int qBase = qt * 64;

#pragma unroll
        for (int it = 0; it < 8; it++) {
            int f4 = tid + it * 128;
            int r = f4 >> 4, c = f4 & 15;
            *(float4*)&Qs[r][c * 4] =
                *(const float4*)&g_q[(bRow + qBase + r) * H_ + c * 4];
        }

        float m_i[8], l_i[8], acc[8][4];
#pragma unroll
        for (int m = 0; m < 8; m++) {
            m_i[m] = -1e30f; l_i[m] = 0.0f;
#pragma unroll
            for (int n = 0; n < 4; n++) acc[m][n] = 0.0f;
        }

        for (int kt = 0; kt <= qt; kt++) {
            const int kvBase = kt * 64;
#pragma unroll
            for (int it = 0; it < 8; it++) {
                int f4 = tid + it * 128;
                int r = f4 >> 4, c = f4 & 15;
                int cp = c ^ (r >> 2);
                *(float4*)&KPs[r][cp * 4] =
                    *(const float4*)&g_k[(bRow + kvBase + r) * H_ + c * 4];
                *(float4*)&Vs[r][c * 4] =
                    *(const float4*)&g_v[(bRow + kvBase + r) * H_ + c * 4];
            }
            __syncthreads();

            float S[8][4];
#pragma unroll
            for (int m = 0; m < 8; m++)
#pragma unroll
                for (int n = 0; n < 4; n++) S[m][n] = 0.0f;

#pragma unroll 4
            for (int h4 = 0; h4 < 16; h4++) {
                float4 kf[4];
#pragma unroll
                for (int n = 0; n < 4; n++)
                    kf[n] = *(const float4*)&KPs[4 * j + n][4 * (h4 ^ j)];
#pragma unroll
                for (int m = 0; m < 8; m++) {
                    float4 a = *(const float4*)&Qs[8 * i + m][4 * h4];
#pragma unroll
                    for (int n = 0; n < 4; n++) {
                        S[m][n] += a.x * kf[n].x;
                        S[m][n] += a.y * kf[n].y;
                        S[m][n] += a.z * kf[n].z;
                        S[m][n] += a.w * kf[n].w;
                    }
                }
            }
            __syncthreads();

            if (kt == qt) {
#pragma unroll
                for (int m = 0; m < 8; m++)
#pragma unroll
                    for (int n = 0; n < 4; n++)
                        if (4 * j + n > 8 * i + m) S[m][n] = -1e30f;
            }

#pragma unroll
            for (int m = 0; m < 8; m++) {
                float rmax = fmaxf(fmaxf(S[m][0], S[m][1]), fmaxf(S[m][2], S[m][3]));
#pragma unroll
                for (int msk = 8; msk >= 1; msk >>= 1)
                    rmax = fmaxf(rmax, __shfl_xor_sync(0xffffffffu, rmax, msk));
                float mNew = fmaxf(m_i[m], rmax);
                float factor = exp2f(m_i[m] - mNew);
                float4 pv;
                pv.x = exp2f(S[m][0] - mNew);
                pv.y = exp2f(S[m][1] - mNew);
                pv.z = exp2f(S[m][2] - mNew);
                pv.w = exp2f(S[m][3] - mNew);
                float rsum = pv.x + pv.y + pv.z + pv.w;
#pragma unroll
                for (int msk = 8; msk >= 1; msk >>= 1)
                    rsum += __shfl_xor_sync(0xffffffffu, rsum, msk);
                l_i[m] = l_i[m] * factor + rsum;
                m_i[m] = mNew;
                acc[m][0] *= factor; acc[m][1] *= factor;
                acc[m][2] *= factor; acc[m][3] *= factor;
                *(float4*)&KPs[8 * i + m][4 * j] = pv;
            }
            __syncthreads();

#pragma unroll 4
            for (int kv4 = 0; kv4 < 16; kv4++) {
                float4 vf[4];
#pragma unroll
                for (int n = 0; n < 4; n++)
                    vf[n] = *(const float4*)&Vs[4 * kv4 + n][4 * j];
#pragma unroll
                for (int m = 0; m < 8; m++) {
                    float4 pm = *(const float4*)&KPs[8 * i + m][4 * kv4];
                    acc[m][0] += pm.x * vf[0].x; acc[m][0] += pm.y * vf[1].x;
                    acc[m][0] += pm.z * vf[2].x; acc[m][0] += pm.w * vf[3].x;
                    acc[m][1] += pm.x * vf[0].y; acc[m][1] += pm.y * vf[1].y;
                    acc[m][1] += pm.z * vf[2].y; acc[m][1] += pm.w * vf[3].y;
                    acc[m][2] += pm.x * vf[0].z; acc[m][2] += pm.y * vf[1].z;
                    acc[m][2] += pm.z * vf[2].z; acc[m][2] += pm.w * vf[3].z;
                    acc[m][3] += pm.x * vf[0].w; acc[m][3] += pm.y * vf[1].w;
                    acc[m][3] += pm.z * vf[2].w; acc[m][3] += pm.w * vf[3].w;
                }
            }
            __syncthreads();
        }

#pragma unroll
        for (int m = 0; m < 8; m++) {
            float inv = 1.0f / l_i[m];
            float4 o;
            o.x = acc[m][0] * inv; o.y = acc[m][1] * inv;
            o.z = acc[m][2] * inv; o.w = acc[m][3] * inv;
            *(float4*)&out[(bRow + qBase + 8 * i + m) * H_ + 4 * j] = o;
        }
        __syncthreads();
    }
}

// ---------------------------------------------------------------------------
extern "C" void kernel_launch(void* const* d_in, const int* in_sizes, int n_in,
                              void* d_out, int out_size)
{
    const float* x  = (const float*)d_in[0];
    const float* wq = (const float*)d_in[1];
    const float* wk = (const float*)d_in[2];
    const float* wv = (const float*)d_in[3];
    float* out = (float*)d_out;

    cudaFuncSetAttribute(qkv_proj_mma,
                         cudaFuncAttributeMaxDynamicSharedMemorySize, PROJ_SMEM);

    convert_w_kernel<<<192, 256>>>(wq, wk, wv);
    qkv_proj_mma<<<ROWS_ / 128, 512, PROJ_SMEM>>>(x);
    attn_kernel<<<B_ * 16, 128>>>(out);
}